// round 7
// baseline (speedup 1.0000x reference)
#include <cuda_runtime.h>
#include <cuda_bf16.h>

// CGA motor sandwich out = grade1(M * P * ~M)[:, :6], Cl(7,1), B=1024.
// Fully warp-autonomous: block=192 (6 warps) per batch, warp k computes out[k].
// No __syncthreads anywhere. Each warp:
//   - writes its own smem motor copy (4 coalesced LDG, __syncwarp only)
//   - builds the point in registers (p-index of stage-1 term j is j itself,
//     so tables store only motor_idx|sign per byte)
//   - computes all 128 odd-grade bins of mx = M*P (4 bins/lane, regs)
//   - out[k] = sum_bins sign'' * mx[bin] * m[b(bin,k)]  (1 byte/term table),
//     5-level shfl reduce, lane 0 stores.

#define NM 127

struct Tables {
    unsigned t1[128 * 2];  // per bin: 2 words = 8 bytes, byte j = a(7b)|neg<<7, pairs p[j]
    unsigned t2[6 * 32];   // [k][lane]: byte i = ent for bin i*32+lane: b(7b)|neg<<7
};

__host__ __device__ constexpr int popc8(int m) {
    int c = 0;
    for (int i = 0; i < 8; i++) c += (m >> i) & 1;
    return c;
}

__host__ __device__ constexpr int sign_of(int a, int b) {
    int s = 1;
    int aa = a >> 1;
    while (aa) { if (popc8(aa & b) & 1) s = -s; aa >>= 1; }
    if ((a & b) & 0x80) s = -s;   // metric: only basis vector 7 squares to -1
    return s;
}

__host__ __device__ constexpr Tables make_tables() {
    Tables T{};
    // masks sorted by (popcount, value) — reference ordering
    int masks[256] = {};
    int t = 0;
    for (int g = 0; g <= 8; ++g)
        for (int m = 0; m < 256; ++m)
            if (popc8(m) == g) masks[t++] = m;

    int mmrank[256] = {};  int nm = 0;
    int oddmask[128] = {}; int nodd = 0;
    for (int i = 0; i < 256; ++i) {
        int m = masks[i], g = popc8(m);
        if ((g & 1) == 0 && m != 255) { mmrank[m] = nm; ++nm; }
        if (g & 1)                    { oddmask[nodd] = m; ++nodd; }
    }

    // stage 1: bin bi, term j pairs p[j] with motor comp rank(mask^ (1<<j))
    for (int bi = 0; bi < 128; ++bi) {
        int rm = oddmask[bi];
        unsigned w0 = 0, w1 = 0;
        for (int j = 0; j < 8; ++j) {
            int am = rm ^ (1 << j);
            unsigned byte = 127;                       // pseudoscalar -> sm[127]==0
            if (am != 255) {
                int s = sign_of(am, 1 << j);
                byte = (unsigned)mmrank[am] | ((s < 0) ? 128u : 0u);
            }
            if (j < 4) w0 |= byte << (8 * j);
            else       w1 |= byte << (8 * (j - 4));
        }
        T.t1[bi * 2]     = w0;
        T.t1[bi * 2 + 1] = w1;
    }

    // stage 2: out blade 1<<k; bin contributes with right operand jm = mask^ (1<<k)
    for (int k = 0; k < 6; ++k) {
        for (int lane = 0; lane < 32; ++lane) {
            unsigned word = 0;
            for (int i = 0; i < 4; ++i) {
                int bi = i * 32 + lane;
                int im = oddmask[bi];
                int jm = im ^ (1 << k);
                unsigned byte = 127;                   // pseudoscalar -> sm[127]==0
                if (jm != 255) {
                    int g  = popc8(jm);
                    int rs = ((g * (g - 1) / 2) & 1) ? -1 : 1;  // reverse sign
                    int s  = sign_of(im, jm) * rs;
                    byte = (unsigned)mmrank[jm] | ((s < 0) ? 128u : 0u);
                }
                word |= byte << (8 * i);
            }
            T.t2[k * 32 + lane] = word;
        }
    }
    return T;
}

__device__ const Tables g_T = make_tables();

__device__ __forceinline__ float with_sign(float v, unsigned e) {
    return __int_as_float(__float_as_int(v) ^ (int)((e & 128u) << 24));
}

__global__ __launch_bounds__(192)
void cga_sandwich_kernel(const float* __restrict__ motor,
                         const float* __restrict__ x,
                         float* __restrict__ out)
{
    __shared__ float s_m[6][128];

    const int t = threadIdx.x;
    const int w = t >> 5, lane = t & 31;   // w = output index k
    const int batch = blockIdx.x;

    float* sm = s_m[w];
    const float* mrow = motor + (size_t)batch * NM;

    // per-warp motor copy (coalesced), pad slot 127 = 0
    #pragma unroll
    for (int i = 0; i < 4; i++) {
        int idx = i * 32 + lane;
        sm[idx] = (idx < NM) ? mrow[idx] : 0.0f;
    }

    // point in registers (every lane): [x0..x5, h-0.5, h+0.5]
    const float* xr = x + (size_t)batch * 6;
    float p0 = __ldg(xr + 0), p1 = __ldg(xr + 1), p2 = __ldg(xr + 2);
    float p3 = __ldg(xr + 3), p4 = __ldg(xr + 4), p5 = __ldg(xr + 5);
    float h = 0.5f * (p0*p0 + p1*p1 + p2*p2 + p3*p3 + p4*p4 + p5*p5);
    float p6 = h - 0.5f, p7 = h + 0.5f;

    __syncwarp();

    // ---- stage 1: all 128 bins, 4 per lane, results in registers ----
    float mx[4];
    #pragma unroll
    for (int i = 0; i < 4; i++) {
        const int bin = i * 32 + lane;
        const uint2 wd = __ldg((const uint2*)(g_T.t1 + bin * 2));
        unsigned e;
        float acc;
        e = wd.x & 255u;          acc  = with_sign(sm[e & 127u], e) * p0;
        e = (wd.x >> 8) & 255u;   acc  = fmaf(with_sign(sm[e & 127u], e), p1, acc);
        e = (wd.x >> 16) & 255u;  acc  = fmaf(with_sign(sm[e & 127u], e), p2, acc);
        e = (wd.x >> 24);         acc  = fmaf(with_sign(sm[e & 127u], e), p3, acc);
        e = wd.y & 255u;          acc  = fmaf(with_sign(sm[e & 127u], e), p4, acc);
        e = (wd.y >> 8) & 255u;   acc  = fmaf(with_sign(sm[e & 127u], e), p5, acc);
        e = (wd.y >> 16) & 255u;  acc  = fmaf(with_sign(sm[e & 127u], e), p6, acc);
        e = (wd.y >> 24);         acc  = fmaf(with_sign(sm[e & 127u], e), p7, acc);
        mx[i] = acc;
    }

    // ---- stage 2: out[w] = sum over this lane's 4 bins, then warp reduce ----
    const unsigned w2 = __ldg(&g_T.t2[w * 32 + lane]);
    float acc;
    {
        unsigned e;
        e = w2 & 255u;          acc = with_sign(mx[0], e) * sm[e & 127u];
        e = (w2 >> 8) & 255u;   acc = fmaf(with_sign(mx[1], e), sm[e & 127u], acc);
        e = (w2 >> 16) & 255u;  acc = fmaf(with_sign(mx[2], e), sm[e & 127u], acc);
        e = (w2 >> 24);         acc = fmaf(with_sign(mx[3], e), sm[e & 127u], acc);
    }

    #pragma unroll
    for (int off = 16; off; off >>= 1)
        acc += __shfl_xor_sync(0xffffffffu, acc, off);

    if (lane == 0)
        out[(size_t)batch * 6 + w] = acc;
}

extern "C" void kernel_launch(void* const* d_in, const int* in_sizes, int n_in,
                              void* d_out, int out_size)
{
    const float* motor = (const float*)d_in[0];   // [B, 127]
    const float* x     = (const float*)d_in[1];   // [B, 6]
    float* out = (float*)d_out;

    int Bn = in_sizes[0] / NM;                    // 1024
    cga_sandwich_kernel<<<Bn, 192>>>(motor, x, out);
}

// round 8
// speedup vs baseline: 1.2083x; 1.2083x over previous
#include <cuda_runtime.h>
#include <cuda_bf16.h>

// CGA motor sandwich out = grade1(M * P * ~M)[:, :6], Cl(7,1), B=1024.
// Compile-time byte tables whose bytes directly index a SIGNED-DUPLICATE
// motor array sm2[256] (sm2[j]=m[j], sm2[j+128]=-m[j], slot 127=0):
// no sign XORs, no masking — table byte -> LDS -> FMA.
//
// Block = 256 threads handles FOUR batches (grid=256):
//   stage 1: thread t computes bin (t&127) of mx for its batch pair (t>>7),
//            one LDG.64 table word serves 2 batches; point in registers
//            (term j of any bin pairs p[j] by construction).
//   stage 2: 24 tasks (4 batches x 6 outputs) over 8 warps, 3 each;
//            127-term dot via 4 FMA/lane + 5-level shfl; lane 0 stores.

#define NM 127

struct Tables {
    unsigned t1[128 * 2];  // bin byte j: sm2 index (a | neg<<7), pairs p[j]
    unsigned t2[6 * 32];   // [k][lane] byte i: sm2 index for bin i*32+lane
};

__host__ __device__ constexpr int popc8(int m) {
    int c = 0;
    for (int i = 0; i < 8; i++) c += (m >> i) & 1;
    return c;
}

__host__ __device__ constexpr int sign_of(int a, int b) {
    int s = 1;
    int aa = a >> 1;
    while (aa) { if (popc8(aa & b) & 1) s = -s; aa >>= 1; }
    if ((a & b) & 0x80) s = -s;   // metric: only basis vector 7 squares to -1
    return s;
}

__host__ __device__ constexpr Tables make_tables() {
    Tables T{};
    // masks sorted by (popcount, value) — reference ordering
    int masks[256] = {};
    int t = 0;
    for (int g = 0; g <= 8; ++g)
        for (int m = 0; m < 256; ++m)
            if (popc8(m) == g) masks[t++] = m;

    int mmrank[256] = {};  int nm = 0;
    int oddmask[128] = {}; int nodd = 0;
    for (int i = 0; i < 256; ++i) {
        int m = masks[i], g = popc8(m);
        if ((g & 1) == 0 && m != 255) { mmrank[m] = nm; ++nm; }
        if (g & 1)                    { oddmask[nodd] = m; ++nodd; }
    }

    // stage 1: bin bi, term j pairs p[j] with motor comp rank(mask ^ (1<<j))
    for (int bi = 0; bi < 128; ++bi) {
        int rm = oddmask[bi];
        unsigned w0 = 0, w1 = 0;
        for (int j = 0; j < 8; ++j) {
            int am = rm ^ (1 << j);
            unsigned byte = 127;                       // pseudoscalar -> sm2[127]==0
            if (am != 255) {
                int s = sign_of(am, 1 << j);
                byte = (unsigned)mmrank[am] | ((s < 0) ? 128u : 0u);
            }
            if (j < 4) w0 |= byte << (8 * j);
            else       w1 |= byte << (8 * (j - 4));
        }
        T.t1[bi * 2]     = w0;
        T.t1[bi * 2 + 1] = w1;
    }

    // stage 2: out blade 1<<k; bin im contributes with right operand jm = im^(1<<k)
    for (int k = 0; k < 6; ++k) {
        for (int lane = 0; lane < 32; ++lane) {
            unsigned word = 0;
            for (int i = 0; i < 4; ++i) {
                int bi = i * 32 + lane;
                int im = oddmask[bi];
                int jm = im ^ (1 << k);
                unsigned byte = 127;                   // pseudoscalar -> sm2[127]==0
                if (jm != 255) {
                    int g  = popc8(jm);
                    int rs = ((g * (g - 1) / 2) & 1) ? -1 : 1;  // reverse sign
                    int s  = sign_of(im, jm) * rs;
                    byte = (unsigned)mmrank[jm] | ((s < 0) ? 128u : 0u);
                }
                word |= byte << (8 * i);
            }
            T.t2[k * 32 + lane] = word;
        }
    }
    return T;
}

__device__ const Tables g_T = make_tables();

__global__ __launch_bounds__(256)
void cga_sandwich_kernel(const float* __restrict__ motor,
                         const float* __restrict__ x,
                         float* __restrict__ out,
                         int Bn)
{
    __shared__ float sm2[4][256];   // signed duplicate motors, 4 batches
    __shared__ float smx[4][128];   // stage-1 result (odd-grade bins)

    const int t  = threadIdx.x;
    const int b0 = blockIdx.x * 4;

    // ---- load motors: 512 (bat,j) slots over 256 threads, signed duplicate ----
    #pragma unroll
    for (int r = 0; r < 2; r++) {
        const int l   = t + r * 256;
        const int bat = l >> 7, j = l & 127;
        const int bb  = (b0 + bat < Bn) ? b0 + bat : Bn - 1;
        float v = (j < NM) ? __ldg(&motor[(size_t)bb * NM + j]) : 0.0f;
        sm2[bat][j]       = v;
        sm2[bat][j + 128] = -v;
    }

    // ---- points for this thread's batch pair (registers) ----
    const int pair = t >> 7;        // warp-uniform
    float p[2][8];
    #pragma unroll
    for (int q = 0; q < 2; q++) {
        const int bq = b0 + pair * 2 + q;
        const float* xr = x + (size_t)((bq < Bn) ? bq : Bn - 1) * 6;
        float v0 = __ldg(xr + 0), v1 = __ldg(xr + 1), v2 = __ldg(xr + 2);
        float v3 = __ldg(xr + 3), v4 = __ldg(xr + 4), v5 = __ldg(xr + 5);
        float h = 0.5f * (v0*v0 + v1*v1 + v2*v2 + v3*v3 + v4*v4 + v5*v5);
        p[q][0] = v0; p[q][1] = v1; p[q][2] = v2;
        p[q][3] = v3; p[q][4] = v4; p[q][5] = v5;
        p[q][6] = h - 0.5f; p[q][7] = h + 0.5f;
    }
    __syncthreads();

    // ---- stage 1: bin (t&127) for both batches of the pair ----
    {
        const int bin = t & 127;
        const uint2 wd = __ldg((const uint2*)(g_T.t1 + bin * 2));
        const float* s0 = sm2[pair * 2];
        const float* s1 = sm2[pair * 2 + 1];
        unsigned e;
        float a0, a1;
        e = wd.x & 255u;         a0 = s0[e] * p[0][0];            a1 = s1[e] * p[1][0];
        e = (wd.x >> 8) & 255u;  a0 = fmaf(s0[e], p[0][1], a0);   a1 = fmaf(s1[e], p[1][1], a1);
        e = (wd.x >> 16) & 255u; a0 = fmaf(s0[e], p[0][2], a0);   a1 = fmaf(s1[e], p[1][2], a1);
        e = wd.x >> 24;          a0 = fmaf(s0[e], p[0][3], a0);   a1 = fmaf(s1[e], p[1][3], a1);
        e = wd.y & 255u;         a0 = fmaf(s0[e], p[0][4], a0);   a1 = fmaf(s1[e], p[1][4], a1);
        e = (wd.y >> 8) & 255u;  a0 = fmaf(s0[e], p[0][5], a0);   a1 = fmaf(s1[e], p[1][5], a1);
        e = (wd.y >> 16) & 255u; a0 = fmaf(s0[e], p[0][6], a0);   a1 = fmaf(s1[e], p[1][6], a1);
        e = wd.y >> 24;          a0 = fmaf(s0[e], p[0][7], a0);   a1 = fmaf(s1[e], p[1][7], a1);
        smx[pair * 2][bin]     = a0;
        smx[pair * 2 + 1][bin] = a1;
    }
    __syncthreads();

    // ---- stage 2: 24 tasks (bat,k) over 8 warps, 3 each ----
    const int w = t >> 5, lane = t & 31;
    #pragma unroll
    for (int it = 0; it < 3; it++) {
        const int tsk = w + it * 8;        // 0..23
        const int bat = tsk & 3, k = tsk >> 2;
        const unsigned wd = __ldg(&g_T.t2[k * 32 + lane]);
        const float* sb  = sm2[bat];
        const float* mxb = smx[bat];
        float acc;
        acc = mxb[lane]      * sb[wd & 255u];
        acc = fmaf(mxb[32 + lane], sb[(wd >> 8)  & 255u], acc);
        acc = fmaf(mxb[64 + lane], sb[(wd >> 16) & 255u], acc);
        acc = fmaf(mxb[96 + lane], sb[wd >> 24],          acc);
        #pragma unroll
        for (int off = 16; off; off >>= 1)
            acc += __shfl_xor_sync(0xffffffffu, acc, off);
        if (lane == 0 && b0 + bat < Bn)
            out[(size_t)(b0 + bat) * 6 + k] = acc;
    }
}

extern "C" void kernel_launch(void* const* d_in, const int* in_sizes, int n_in,
                              void* d_out, int out_size)
{
    const float* motor = (const float*)d_in[0];   // [B, 127]
    const float* x     = (const float*)d_in[1];   // [B, 6]
    float* out = (float*)d_out;

    int Bn = in_sizes[0] / NM;                    // 1024
    int grid = (Bn + 3) / 4;                      // 4 batches per 256-thread block
    cga_sandwich_kernel<<<grid, 256>>>(motor, x, out, Bn);
}

// round 9
// speedup vs baseline: 1.2196x; 1.0093x over previous
#include <cuda_runtime.h>
#include <cuda_bf16.h>

// CGA motor sandwich out = grade1(M * P * ~M)[:, :6], Cl(7,1), B=1024.
// Compile-time byte tables index a SIGNED-DUPLICATE motor array sm2[256]
// (sm2[j]=m[j], sm2[j+128]=-m[j], slot 127=0): table byte -> LDS -> FMA,
// no sign ops at runtime.
//
// Block = 384 threads (12 warps) handles TWO batches (grid = 512):
//   head:    threads 0..255 load motor (1 LDG each, signed-dup STS) and
//            their batch's point into registers (3x LDG.64).
//   stage 1: thread t<256 computes bin (t&127) of mx for batch (t>>7).
//   stage 2: 12 tasks (2 batches x 6 outputs) = ONE per warp; 127-term dot
//            via 4 FMA/lane + single 5-level shfl chain; lane 0 stores.

#define NM 127

struct Tables {
    unsigned t1[128 * 2];  // bin byte j: sm2 index (a | neg<<7), pairs p[j]
    unsigned t2[6 * 32];   // [k][lane] byte i: sm2 index for bin i*32+lane
};

__host__ __device__ constexpr int popc8(int m) {
    int c = 0;
    for (int i = 0; i < 8; i++) c += (m >> i) & 1;
    return c;
}

__host__ __device__ constexpr int sign_of(int a, int b) {
    int s = 1;
    int aa = a >> 1;
    while (aa) { if (popc8(aa & b) & 1) s = -s; aa >>= 1; }
    if ((a & b) & 0x80) s = -s;   // metric: only basis vector 7 squares to -1
    return s;
}

__host__ __device__ constexpr Tables make_tables() {
    Tables T{};
    // masks sorted by (popcount, value) — reference ordering
    int masks[256] = {};
    int t = 0;
    for (int g = 0; g <= 8; ++g)
        for (int m = 0; m < 256; ++m)
            if (popc8(m) == g) masks[t++] = m;

    int mmrank[256] = {};  int nm = 0;
    int oddmask[128] = {}; int nodd = 0;
    for (int i = 0; i < 256; ++i) {
        int m = masks[i], g = popc8(m);
        if ((g & 1) == 0 && m != 255) { mmrank[m] = nm; ++nm; }
        if (g & 1)                    { oddmask[nodd] = m; ++nodd; }
    }

    // stage 1: bin bi, term j pairs p[j] with motor comp rank(mask ^ (1<<j))
    for (int bi = 0; bi < 128; ++bi) {
        int rm = oddmask[bi];
        unsigned w0 = 0, w1 = 0;
        for (int j = 0; j < 8; ++j) {
            int am = rm ^ (1 << j);
            unsigned byte = 127;                       // pseudoscalar -> sm2[127]==0
            if (am != 255) {
                int s = sign_of(am, 1 << j);
                byte = (unsigned)mmrank[am] | ((s < 0) ? 128u : 0u);
            }
            if (j < 4) w0 |= byte << (8 * j);
            else       w1 |= byte << (8 * (j - 4));
        }
        T.t1[bi * 2]     = w0;
        T.t1[bi * 2 + 1] = w1;
    }

    // stage 2: out blade 1<<k; bin im contributes with right operand jm = im^(1<<k)
    for (int k = 0; k < 6; ++k) {
        for (int lane = 0; lane < 32; ++lane) {
            unsigned word = 0;
            for (int i = 0; i < 4; ++i) {
                int bi = i * 32 + lane;
                int im = oddmask[bi];
                int jm = im ^ (1 << k);
                unsigned byte = 127;                   // pseudoscalar -> sm2[127]==0
                if (jm != 255) {
                    int g  = popc8(jm);
                    int rs = ((g * (g - 1) / 2) & 1) ? -1 : 1;  // reverse sign
                    int s  = sign_of(im, jm) * rs;
                    byte = (unsigned)mmrank[jm] | ((s < 0) ? 128u : 0u);
                }
                word |= byte << (8 * i);
            }
            T.t2[k * 32 + lane] = word;
        }
    }
    return T;
}

__device__ const Tables g_T = make_tables();

__global__ __launch_bounds__(384)
void cga_sandwich_kernel(const float* __restrict__ motor,
                         const float* __restrict__ x,
                         float* __restrict__ out,
                         int Bn)
{
    __shared__ float sm2[2][256];   // signed duplicate motors, 2 batches
    __shared__ float smx[2][128];   // stage-1 result (odd-grade bins)

    const int t  = threadIdx.x;
    const int b0 = blockIdx.x * 2;

    const int bat = (t >> 7) & 1;   // batch owned in head/stage-1 (t<256)
    const int j   = t & 127;

    if (t < 256) {
        // motor load: 1 coalesced LDG per thread, signed-duplicate store
        const int bb = (b0 + bat < Bn) ? b0 + bat : Bn - 1;
        float v = (j < NM) ? __ldg(&motor[(size_t)bb * NM + j]) : 0.0f;
        sm2[bat][j]       = v;
        sm2[bat][j + 128] = -v;
    }

    // point for this thread's batch (registers), 3x LDG.64
    float p[8];
    if (t < 256) {
        const int bq = b0 + bat;
        const float2* xr = (const float2*)(x + (size_t)((bq < Bn) ? bq : Bn - 1) * 6);
        float2 v01 = __ldg(xr), v23 = __ldg(xr + 1), v45 = __ldg(xr + 2);
        float h = 0.5f * (v01.x*v01.x + v01.y*v01.y + v23.x*v23.x +
                          v23.y*v23.y + v45.x*v45.x + v45.y*v45.y);
        p[0] = v01.x; p[1] = v01.y; p[2] = v23.x;
        p[3] = v23.y; p[4] = v45.x; p[5] = v45.y;
        p[6] = h - 0.5f; p[7] = h + 0.5f;
    }
    __syncthreads();

    // ---- stage 1: thread t<256 computes bin j of mx for its batch ----
    if (t < 256) {
        const uint2 wd = __ldg((const uint2*)(g_T.t1 + j * 2));
        const float* s = sm2[bat];
        unsigned e;
        float a;
        e = wd.x & 255u;         a = s[e] * p[0];
        e = (wd.x >> 8) & 255u;  a = fmaf(s[e], p[1], a);
        e = (wd.x >> 16) & 255u; a = fmaf(s[e], p[2], a);
        e = wd.x >> 24;          a = fmaf(s[e], p[3], a);
        e = wd.y & 255u;         a = fmaf(s[e], p[4], a);
        e = (wd.y >> 8) & 255u;  a = fmaf(s[e], p[5], a);
        e = (wd.y >> 16) & 255u; a = fmaf(s[e], p[6], a);
        e = wd.y >> 24;          a = fmaf(s[e], p[7], a);
        smx[bat][j] = a;
    }
    __syncthreads();

    // ---- stage 2: ONE task per warp: warp w -> (batch w>=6, output w%6) ----
    const int w = t >> 5, lane = t & 31;
    const int bat2 = (w >= 6) ? 1 : 0;
    const int k    = w - bat2 * 6;
    const unsigned wd = __ldg(&g_T.t2[k * 32 + lane]);
    const float* sb  = sm2[bat2];
    const float* mxb = smx[bat2];
    float acc;
    acc = mxb[lane]            * sb[wd & 255u];
    acc = fmaf(mxb[32 + lane], sb[(wd >> 8)  & 255u], acc);
    acc = fmaf(mxb[64 + lane], sb[(wd >> 16) & 255u], acc);
    acc = fmaf(mxb[96 + lane], sb[wd >> 24],          acc);
    #pragma unroll
    for (int off = 16; off; off >>= 1)
        acc += __shfl_xor_sync(0xffffffffu, acc, off);
    if (lane == 0 && b0 + bat2 < Bn)
        out[(size_t)(b0 + bat2) * 6 + k] = acc;
}

extern "C" void kernel_launch(void* const* d_in, const int* in_sizes, int n_in,
                              void* d_out, int out_size)
{
    const float* motor = (const float*)d_in[0];   // [B, 127]
    const float* x     = (const float*)d_in[1];   // [B, 6]
    float* out = (float*)d_out;

    int Bn = in_sizes[0] / NM;                    // 1024
    int grid = (Bn + 1) / 2;                      // 2 batches per 384-thread block
    cga_sandwich_kernel<<<grid, 384>>>(motor, x, out, Bn);
}

// round 10
// speedup vs baseline: 1.3454x; 1.1031x over previous
#include <cuda_runtime.h>
#include <cuda_bf16.h>

// CGA motor sandwich out = grade1(M * P * ~M)[:, :6], Cl(7,1), B=1024.
// Compile-time byte tables index a SIGNED-DUPLICATE motor array sm2[256]
// (sm2[j]=m[j], sm2[j+128]=-m[j], slot 127=0): table byte -> LDS -> FMA,
// no sign ops at runtime.
//
// Block = 768 threads (24 warps), FOUR batches per block (grid = 256):
//   head (t<512):  bat=t>>7, j=t&127: motor LDG + signed-dup STS;
//                  point in registers (3x LDG.64); t1 word prefetched.
//   stage 1 (t<512): bin j of mx for batch bat (8 LDS + 8 FMA).
//   stage 2: 24 tasks (4 batches x 6 outputs) = exactly ONE per warp;
//            127-term dot: 4 LDS-pairs + 4 FMA + one 5-level shfl chain.

#define NM 127

struct Tables {
    unsigned t1[128 * 2];  // bin byte j: sm2 index (a | neg<<7), pairs p[j]
    unsigned t2[6 * 32];   // [k][lane] byte i: sm2 index for bin i*32+lane
};

__host__ __device__ constexpr int popc8(int m) {
    int c = 0;
    for (int i = 0; i < 8; i++) c += (m >> i) & 1;
    return c;
}

__host__ __device__ constexpr int sign_of(int a, int b) {
    int s = 1;
    int aa = a >> 1;
    while (aa) { if (popc8(aa & b) & 1) s = -s; aa >>= 1; }
    if ((a & b) & 0x80) s = -s;   // metric: only basis vector 7 squares to -1
    return s;
}

__host__ __device__ constexpr Tables make_tables() {
    Tables T{};
    // masks sorted by (popcount, value) — reference ordering
    int masks[256] = {};
    int t = 0;
    for (int g = 0; g <= 8; ++g)
        for (int m = 0; m < 256; ++m)
            if (popc8(m) == g) masks[t++] = m;

    int mmrank[256] = {};  int nm = 0;
    int oddmask[128] = {}; int nodd = 0;
    for (int i = 0; i < 256; ++i) {
        int m = masks[i], g = popc8(m);
        if ((g & 1) == 0 && m != 255) { mmrank[m] = nm; ++nm; }
        if (g & 1)                    { oddmask[nodd] = m; ++nodd; }
    }

    // stage 1: bin bi, term j pairs p[j] with motor comp rank(mask ^ (1<<j))
    for (int bi = 0; bi < 128; ++bi) {
        int rm = oddmask[bi];
        unsigned w0 = 0, w1 = 0;
        for (int j = 0; j < 8; ++j) {
            int am = rm ^ (1 << j);
            unsigned byte = 127;                       // pseudoscalar -> sm2[127]==0
            if (am != 255) {
                int s = sign_of(am, 1 << j);
                byte = (unsigned)mmrank[am] | ((s < 0) ? 128u : 0u);
            }
            if (j < 4) w0 |= byte << (8 * j);
            else       w1 |= byte << (8 * (j - 4));
        }
        T.t1[bi * 2]     = w0;
        T.t1[bi * 2 + 1] = w1;
    }

    // stage 2: out blade 1<<k; bin im contributes with right operand jm = im^(1<<k)
    for (int k = 0; k < 6; ++k) {
        for (int lane = 0; lane < 32; ++lane) {
            unsigned word = 0;
            for (int i = 0; i < 4; ++i) {
                int bi = i * 32 + lane;
                int im = oddmask[bi];
                int jm = im ^ (1 << k);
                unsigned byte = 127;                   // pseudoscalar -> sm2[127]==0
                if (jm != 255) {
                    int g  = popc8(jm);
                    int rs = ((g * (g - 1) / 2) & 1) ? -1 : 1;  // reverse sign
                    int s  = sign_of(im, jm) * rs;
                    byte = (unsigned)mmrank[jm] | ((s < 0) ? 128u : 0u);
                }
                word |= byte << (8 * i);
            }
            T.t2[k * 32 + lane] = word;
        }
    }
    return T;
}

__device__ const Tables g_T = make_tables();

__global__ __launch_bounds__(768)
void cga_sandwich_kernel(const float* __restrict__ motor,
                         const float* __restrict__ x,
                         float* __restrict__ out,
                         int Bn)
{
    __shared__ float sm2[4][256];   // signed-duplicate motors, 4 batches
    __shared__ float smx[4][128];   // stage-1 result (odd-grade bins)

    const int t  = threadIdx.x;
    const int b0 = blockIdx.x * 4;
    const int w  = t >> 5, lane = t & 31;

    // stage-2 task for THIS warp (prefetch its table word now: no smem dep)
    const int bat2 = w / 6;            // 0..3
    const int k    = w - bat2 * 6;     // 0..5
    const unsigned wd2 = __ldg(&g_T.t2[k * 32 + lane]);

    const int bat = (t >> 7) & 3;      // head batch (t<512)
    const int j   = t & 127;

    float p[8];
    uint2 wd1 = make_uint2(0u, 0u);

    if (t < 512) {
        // motor load: 1 coalesced LDG per thread, signed-duplicate store
        const int bb = (b0 + bat < Bn) ? b0 + bat : Bn - 1;
        float v = (j < NM) ? __ldg(&motor[(size_t)bb * NM + j]) : 0.0f;
        sm2[bat][j]       = v;
        sm2[bat][j + 128] = -v;

        // stage-1 table word (prefetch; independent of smem)
        wd1 = __ldg((const uint2*)(g_T.t1 + j * 2));

        // point for this thread's batch (registers), 3x LDG.64
        const float2* xr = (const float2*)(x + (size_t)bb * 6);
        float2 v01 = __ldg(xr), v23 = __ldg(xr + 1), v45 = __ldg(xr + 2);
        float h = 0.5f * (v01.x*v01.x + v01.y*v01.y + v23.x*v23.x +
                          v23.y*v23.y + v45.x*v45.x + v45.y*v45.y);
        p[0] = v01.x; p[1] = v01.y; p[2] = v23.x;
        p[3] = v23.y; p[4] = v45.x; p[5] = v45.y;
        p[6] = h - 0.5f; p[7] = h + 0.5f;
    }
    __syncthreads();

    // ---- stage 1: thread t<512 computes bin j of mx for its batch ----
    if (t < 512) {
        const float* s = sm2[bat];
        unsigned e;
        float a;
        e = wd1.x & 255u;         a = s[e] * p[0];
        e = (wd1.x >> 8) & 255u;  a = fmaf(s[e], p[1], a);
        e = (wd1.x >> 16) & 255u; a = fmaf(s[e], p[2], a);
        e = wd1.x >> 24;          a = fmaf(s[e], p[3], a);
        e = wd1.y & 255u;         a = fmaf(s[e], p[4], a);
        e = (wd1.y >> 8) & 255u;  a = fmaf(s[e], p[5], a);
        e = (wd1.y >> 16) & 255u; a = fmaf(s[e], p[6], a);
        e = wd1.y >> 24;          a = fmaf(s[e], p[7], a);
        smx[bat][j] = a;
    }
    __syncthreads();

    // ---- stage 2: ONE task per warp ----
    const float* sb  = sm2[bat2];
    const float* mxb = smx[bat2];
    float acc;
    acc = mxb[lane]            * sb[wd2 & 255u];
    acc = fmaf(mxb[32 + lane], sb[(wd2 >> 8)  & 255u], acc);
    acc = fmaf(mxb[64 + lane], sb[(wd2 >> 16) & 255u], acc);
    acc = fmaf(mxb[96 + lane], sb[wd2 >> 24],          acc);
    #pragma unroll
    for (int off = 16; off; off >>= 1)
        acc += __shfl_xor_sync(0xffffffffu, acc, off);
    if (lane == 0 && b0 + bat2 < Bn)
        out[(size_t)(b0 + bat2) * 6 + k] = acc;
}

extern "C" void kernel_launch(void* const* d_in, const int* in_sizes, int n_in,
                              void* d_out, int out_size)
{
    const float* motor = (const float*)d_in[0];   // [B, 127]
    const float* x     = (const float*)d_in[1];   // [B, 6]
    float* out = (float*)d_out;

    int Bn = in_sizes[0] / NM;                    // 1024
    int grid = (Bn + 3) / 4;                      // 4 batches per 768-thread block
    cga_sandwich_kernel<<<grid, 768>>>(motor, x, out, Bn);
}